// round 12
// baseline (speedup 1.0000x reference)
#include <cuda_runtime.h>
#include <cstdint>

// GHMRankingLoss, fused single kernel. LDG demand path + bulk L2 prefetch.
//
//   result = (1/N) * sum_{b=5..9} max(cnt_b,1)^-0.75 * S_b   (bins 0-4: loss==0)
// u = -t*diff; since t^2 == 1, the sigmoid arg x = u*(2-t) == 2u + diff (1 FFMA).
// Cumulative tallies C_k = sum_{x>=T_k} u, N_k = #{x>=T_k} over
// T = {0, ln(6/4), ln(7/3), ln(8/2), ln(9/1)}; per-bin values by differencing.
// FSET -> {0,1} float, FFMA accumulate (exact); counts in INT on the alu pipe.
//
// Prefetch: PD=2 -> steady-state L2 window = 888 * 4 * 3 * 4KB ~= 41MB (1/3 of
// L2; PD=6 thrashed at 125MB, PD=3 = 62MB still tight under CTA skew). All six
// 4KB chunk prefetches issue in ONE warp-instruction slot via lanes 0..5
// (cp.async.bulk.prefetch is per-thread), removing the old tid==0 serial chain.

#define NT 256
#define NB 888    // 6 CTAs/SM * 148 SMs
#define K  5
#define PD 2      // prefetch distance, in unroll-2 iterations (L2-window-sized)

__device__ float2 g_part[K * NB];   // k-major: [k][block] = (C_k, N_k)
__device__ unsigned int g_ticket;   // zero at load; last block resets

__device__ __forceinline__ void pf_l2(const void* p) {
    // 4 KB = one CTA-iteration chunk (256 threads * 16 B)
    asm volatile("cp.async.bulk.prefetch.L2.global [%0], %1;"
                 :: "l"(p), "r"(4096) : "memory");
}

__device__ __forceinline__ float fset_ge(float x, float T) {
    float r;
    asm("set.ge.f32.f32 %0, %1, %2;" : "=f"(r) : "f"(x), "f"(T));
    return r;   // 1.0f if x >= T else 0.0f
}

__device__ __forceinline__ void ghm_accum(
    float& c0, float& c1, float& c2, float& c3, float& c4,
    int& n0, int& n1, int& n2, int& n3, int& n4,
    float a, float b, float t) {
    float diff = a - b;
    float u = -t * diff;              // == loss whenever u >= 0
    float x = fmaf(2.0f, u, diff);    // == u*(2-t) since t*t == 1
    float r0 = fset_ge(x, 0.0f);
    float r1 = fset_ge(x, 0.40546511f);   // ln(6/4)
    float r2 = fset_ge(x, 0.84729786f);   // ln(7/3)
    float r3 = fset_ge(x, 1.38629436f);   // ln(8/2)
    float r4 = fset_ge(x, 2.19722458f);   // ln(9/1)
    // loss sums on the fma pipe, counts on the alu pipe (int compares of x)
    c0 = fmaf(r0, u, c0);  n0 += (x >= 0.0f);
    c1 = fmaf(r1, u, c1);  n1 += (x >= 0.40546511f);
    c2 = fmaf(r2, u, c2);  n2 += (x >= 0.84729786f);
    c3 = fmaf(r3, u, c3);  n3 += (x >= 1.38629436f);
    c4 = fmaf(r4, u, c4);  n4 += (x >= 2.19722458f);
}
#define ACC(av, bv, tv) ghm_accum(c0,c1,c2,c3,c4,n0,n1,n2,n3,n4, av, bv, tv)

__global__ void __launch_bounds__(NT, 6)
ghm_fused_k(const float* __restrict__ o1,
            const float* __restrict__ o2,
            const float* __restrict__ tg,
            float* __restrict__ out,
            int n) {
    const int tid = threadIdx.x;
    const int bid = blockIdx.x;

    float c0 = 0.f, c1 = 0.f, c2 = 0.f, c3 = 0.f, c4 = 0.f;
    int   n0 = 0,   n1 = 0,   n2 = 0,   n3 = 0,   n4 = 0;

    const int n4e    = n >> 2;
    const int stride = NB * NT;
    int i = bid * NT + tid;

    const float4* __restrict__ A = (const float4*)o1;
    const float4* __restrict__ B = (const float4*)o2;
    const float4* __restrict__ T = (const float4*)tg;

    // lane-indexed prefetch targets: lane l -> array l/2, sub-chunk l%2
    const float4* __restrict__ PFA[3] = {A, B, T};
    const int pf_arr = tid >> 1;      // 0,1,2 for lanes 0..5
    const int pf_sub = tid & 1;       // 0,1

    // warm the L2 window for the first PD iterations (lanes 0..5, one slot/iter)
    if (tid < 6) {
        for (int d = 0; d < PD; d++) {
            int pf = bid * NT + (2 * d + pf_sub) * stride;
            if (pf < n4e) pf_l2(PFA[pf_arr] + pf);
        }
    }

    // unroll-2: 6 front-batched LDG.128 per iteration; prefetch PD iters ahead.
    // All 6 prefetches issue in a single warp-instruction (lanes 0..5).
    for (; i + stride < n4e; i += 2 * stride) {
        if (tid < 6) {
            int pf = (i - tid) + (PD * 2 + pf_sub) * stride;   // i - tid == bid*NT + k*2*stride
            if (pf < n4e) pf_l2(PFA[pf_arr] + pf);
        }
        float4 a0 = __ldcs(A + i);
        float4 b0 = __ldcs(B + i);
        float4 t0 = __ldcs(T + i);
        float4 a1 = __ldcs(A + i + stride);
        float4 b1 = __ldcs(B + i + stride);
        float4 t1 = __ldcs(T + i + stride);
        ACC(a0.x, b0.x, t0.x);  ACC(a0.y, b0.y, t0.y);
        ACC(a0.z, b0.z, t0.z);  ACC(a0.w, b0.w, t0.w);
        ACC(a1.x, b1.x, t1.x);  ACC(a1.y, b1.y, t1.y);
        ACC(a1.z, b1.z, t1.z);  ACC(a1.w, b1.w, t1.w);
    }
    for (; i < n4e; i += stride) {
        float4 a = __ldcs(A + i);
        float4 b = __ldcs(B + i);
        float4 t = __ldcs(T + i);
        ACC(a.x, b.x, t.x);  ACC(a.y, b.y, t.y);
        ACC(a.z, b.z, t.z);  ACC(a.w, b.w, t.w);
    }
    for (int j = (n4e << 2) + bid * NT + tid; j < n; j += stride)
        ACC(o1[j], o2[j], tg[j]);

    // ---- block reduce: warp shfl, then cross-warp via smem ----
    float cs[K] = {c0, c1, c2, c3, c4};
    float ns[K] = {(float)n0, (float)n1, (float)n2, (float)n3, (float)n4};
    #pragma unroll
    for (int off = 16; off; off >>= 1) {
        #pragma unroll
        for (int k = 0; k < K; k++) {
            cs[k] += __shfl_down_sync(0xffffffff, cs[k], off);
            ns[k] += __shfl_down_sync(0xffffffff, ns[k], off);
        }
    }

    __shared__ float sC[K][NT / 32], sN[K][NT / 32];
    const int warp = tid >> 5, lane = tid & 31;
    if (lane == 0) {
        #pragma unroll
        for (int k = 0; k < K; k++) { sC[k][warp] = cs[k]; sN[k][warp] = ns[k]; }
    }
    __syncthreads();

    if (tid < K) {
        float c = 0.f, nn = 0.f;
        #pragma unroll
        for (int w = 0; w < NT / 32; w++) { c += sC[tid][w]; nn += sN[tid][w]; }
        g_part[tid * NB + bid] = make_float2(c, nn);
    }

    // ---- ticket: last block finalizes ----
    __shared__ bool isLast;
    __threadfence();
    if (tid == 0) {
        unsigned int v = atomicAdd(&g_ticket, 1u);
        isLast = (v == NB - 1);
    }
    __syncthreads();
    if (!isLast) return;

    __shared__ double ss[K], cc[K];
    if (warp < K) {
        double s = 0.0, c = 0.0;
        for (int j = lane; j < NB; j += 32) {
            float2 p = g_part[warp * NB + j];   // L2-resident
            s += (double)p.x;
            c += (double)p.y;
        }
        #pragma unroll
        for (int off = 16; off; off >>= 1) {
            s += __shfl_down_sync(0xffffffff, s, off);
            c += __shfl_down_sync(0xffffffff, c, off);
        }
        if (lane == 0) { ss[warp] = s; cc[warp] = c; }
    }
    __syncthreads();

    if (tid == 0) {
        double acc = 0.0;
        #pragma unroll
        for (int m = 0; m < K; m++) {
            double Sm  = ss[m] - ((m + 1 < K) ? ss[m + 1] : 0.0);  // bin 5+m loss sum
            double cnt = cc[m] - ((m + 1 < K) ? cc[m + 1] : 0.0);  // bin 5+m count
            double tot = cnt < 1.0 ? 1.0 : cnt;                    // clamp(min=1)
            acc += pow(tot, -0.75) * Sm;                           // w = tot^-alpha
        }
        out[0] = (float)(acc / (double)n);
        g_ticket = 0;                                               // graph-replay safe
    }
}

extern "C" void kernel_launch(void* const* d_in, const int* in_sizes, int n_in,
                              void* d_out, int out_size) {
    const float* o1 = (const float*)d_in[0];
    const float* o2 = (const float*)d_in[1];
    const float* tg = (const float*)d_in[2];
    float* out = (float*)d_out;
    int n = in_sizes[0];

    ghm_fused_k<<<NB, NT>>>(o1, o2, tg, out, n);
}

// round 13
// speedup vs baseline: 1.1907x; 1.1907x over previous
#include <cuda_runtime.h>
#include <cstdint>

// GHMRankingLoss, fused single kernel. LDG demand path + bulk L2 prefetch.
// (R11 structure restored exactly; single change: PD 3 -> 2.)
//
//   result = (1/N) * sum_{b=5..9} max(cnt_b,1)^-0.75 * S_b   (bins 0-4: loss==0)
// u = -t*diff; since t^2 == 1, the sigmoid arg x = u*(2-t) == 2u + diff (1 FFMA).
// Cumulative tallies C_k = sum_{x>=T_k} u, N_k = #{x>=T_k} over
// T = {0, ln(6/4), ln(7/3), ln(8/2), ln(9/1)}; per-bin values by differencing.
// FSET -> {0,1} float, FFMA accumulate (exact), FADD count (one compare per
// threshold -- the FSET result feeds BOTH accumulators).
//
// Prefetch window: NB * PD*2 chunks * 3 arrays * 4KB.
//   PD=6 -> 125MB (all of L2, thrashed). PD=3 -> 62MB (won, 52.0us).
//   PD=2 -> 41MB (~1/3 of L2): same latency coverage, more capacity slack.

#define NT 256
#define NB 888    // 6 CTAs/SM * 148 SMs
#define K  5
#define PD 2      // prefetch distance, in unroll-2 iterations (L2-window-sized)

__device__ float2 g_part[K * NB];   // k-major: [k][block] = (C_k, N_k)
__device__ unsigned int g_ticket;   // zero at load; last block resets

__device__ __forceinline__ void pf_l2(const void* p) {
    // 4 KB = one CTA-iteration chunk (256 threads * 16 B)
    asm volatile("cp.async.bulk.prefetch.L2.global [%0], %1;"
                 :: "l"(p), "r"(4096) : "memory");
}

__device__ __forceinline__ float fset_ge(float x, float T) {
    float r;
    asm("set.ge.f32.f32 %0, %1, %2;" : "=f"(r) : "f"(x), "f"(T));
    return r;   // 1.0f if x >= T else 0.0f
}

__device__ __forceinline__ void ghm_accum(
    float& c0, float& c1, float& c2, float& c3, float& c4,
    float& n0, float& n1, float& n2, float& n3, float& n4,
    float a, float b, float t) {
    float diff = a - b;
    float u = -t * diff;              // == loss whenever u >= 0
    float x = fmaf(2.0f, u, diff);    // == u*(2-t) since t*t == 1
    float r0 = fset_ge(x, 0.0f);
    float r1 = fset_ge(x, 0.40546511f);   // ln(6/4)
    float r2 = fset_ge(x, 0.84729786f);   // ln(7/3)
    float r3 = fset_ge(x, 1.38629436f);   // ln(8/2)
    float r4 = fset_ge(x, 2.19722458f);   // ln(9/1)
    c0 = fmaf(r0, u, c0);  n0 += r0;
    c1 = fmaf(r1, u, c1);  n1 += r1;
    c2 = fmaf(r2, u, c2);  n2 += r2;
    c3 = fmaf(r3, u, c3);  n3 += r3;
    c4 = fmaf(r4, u, c4);  n4 += r4;
}
#define ACC(av, bv, tv) ghm_accum(c0,c1,c2,c3,c4,n0,n1,n2,n3,n4, av, bv, tv)

__global__ void __launch_bounds__(NT, 6)
ghm_fused_k(const float* __restrict__ o1,
            const float* __restrict__ o2,
            const float* __restrict__ tg,
            float* __restrict__ out,
            int n) {
    const int tid = threadIdx.x;
    const int bid = blockIdx.x;

    float c0 = 0.f, c1 = 0.f, c2 = 0.f, c3 = 0.f, c4 = 0.f;
    float n0 = 0.f, n1 = 0.f, n2 = 0.f, n3 = 0.f, n4 = 0.f;

    const int n4e    = n >> 2;
    const int stride = NB * NT;
    int i = bid * NT + tid;

    const float4* __restrict__ A = (const float4*)o1;
    const float4* __restrict__ B = (const float4*)o2;
    const float4* __restrict__ T = (const float4*)tg;

    // warm the L2 window for the first PD iterations
    if (tid == 0) {
        for (int d = 0; d < 2 * PD; d++) {
            int pf = bid * NT + d * stride;
            if (pf < n4e) { pf_l2(A + pf); pf_l2(B + pf); pf_l2(T + pf); }
        }
    }

    // unroll-2: 6 front-batched LDG.128 per iteration; prefetch PD iters ahead
    for (; i + stride < n4e; i += 2 * stride) {
        if (tid == 0) {
            int pf = i + PD * 2 * stride;
            if (pf < n4e) { pf_l2(A + pf); pf_l2(B + pf); pf_l2(T + pf); }
            pf += stride;
            if (pf < n4e) { pf_l2(A + pf); pf_l2(B + pf); pf_l2(T + pf); }
        }
        float4 a0 = __ldcs(A + i);
        float4 b0 = __ldcs(B + i);
        float4 t0 = __ldcs(T + i);
        float4 a1 = __ldcs(A + i + stride);
        float4 b1 = __ldcs(B + i + stride);
        float4 t1 = __ldcs(T + i + stride);
        ACC(a0.x, b0.x, t0.x);  ACC(a0.y, b0.y, t0.y);
        ACC(a0.z, b0.z, t0.z);  ACC(a0.w, b0.w, t0.w);
        ACC(a1.x, b1.x, t1.x);  ACC(a1.y, b1.y, t1.y);
        ACC(a1.z, b1.z, t1.z);  ACC(a1.w, b1.w, t1.w);
    }
    for (; i < n4e; i += stride) {
        float4 a = __ldcs(A + i);
        float4 b = __ldcs(B + i);
        float4 t = __ldcs(T + i);
        ACC(a.x, b.x, t.x);  ACC(a.y, b.y, t.y);
        ACC(a.z, b.z, t.z);  ACC(a.w, b.w, t.w);
    }
    for (int j = (n4e << 2) + bid * NT + tid; j < n; j += stride)
        ACC(o1[j], o2[j], tg[j]);

    // ---- block reduce: warp shfl, then cross-warp via smem ----
    float cs[K] = {c0, c1, c2, c3, c4};
    float ns[K] = {n0, n1, n2, n3, n4};
    #pragma unroll
    for (int off = 16; off; off >>= 1) {
        #pragma unroll
        for (int k = 0; k < K; k++) {
            cs[k] += __shfl_down_sync(0xffffffff, cs[k], off);
            ns[k] += __shfl_down_sync(0xffffffff, ns[k], off);
        }
    }

    __shared__ float sC[K][NT / 32], sN[K][NT / 32];
    const int warp = tid >> 5, lane = tid & 31;
    if (lane == 0) {
        #pragma unroll
        for (int k = 0; k < K; k++) { sC[k][warp] = cs[k]; sN[k][warp] = ns[k]; }
    }
    __syncthreads();

    if (tid < K) {
        float c = 0.f, nn = 0.f;
        #pragma unroll
        for (int w = 0; w < NT / 32; w++) { c += sC[tid][w]; nn += sN[tid][w]; }
        g_part[tid * NB + bid] = make_float2(c, nn);
    }

    // ---- ticket: last block finalizes ----
    __shared__ bool isLast;
    __threadfence();
    if (tid == 0) {
        unsigned int v = atomicAdd(&g_ticket, 1u);
        isLast = (v == NB - 1);
    }
    __syncthreads();
    if (!isLast) return;

    __shared__ double ss[K], cc[K];
    if (warp < K) {
        double s = 0.0, c = 0.0;
        for (int j = lane; j < NB; j += 32) {
            float2 p = g_part[warp * NB + j];   // L2-resident
            s += (double)p.x;
            c += (double)p.y;
        }
        #pragma unroll
        for (int off = 16; off; off >>= 1) {
            s += __shfl_down_sync(0xffffffff, s, off);
            c += __shfl_down_sync(0xffffffff, c, off);
        }
        if (lane == 0) { ss[warp] = s; cc[warp] = c; }
    }
    __syncthreads();

    if (tid == 0) {
        double acc = 0.0;
        #pragma unroll
        for (int m = 0; m < K; m++) {
            double Sm  = ss[m] - ((m + 1 < K) ? ss[m + 1] : 0.0);  // bin 5+m loss sum
            double cnt = cc[m] - ((m + 1 < K) ? cc[m + 1] : 0.0);  // bin 5+m count
            double tot = cnt < 1.0 ? 1.0 : cnt;                    // clamp(min=1)
            acc += pow(tot, -0.75) * Sm;                           // w = tot^-alpha
        }
        out[0] = (float)(acc / (double)n);
        g_ticket = 0;                                               // graph-replay safe
    }
}

extern "C" void kernel_launch(void* const* d_in, const int* in_sizes, int n_in,
                              void* d_out, int out_size) {
    const float* o1 = (const float*)d_in[0];
    const float* o2 = (const float*)d_in[1];
    const float* tg = (const float*)d_in[2];
    float* out = (float*)d_out;
    int n = in_sizes[0];

    ghm_fused_k<<<NB, NT>>>(o1, o2, tg, out, n);
}